// round 14
// baseline (speedup 1.0000x reference)
#include <cuda_runtime.h>
#include <cuda_bf16.h>
#include <cstdint>
#include <cstddef>
#include <cstring>

// ---------------- problem constants ----------------
#define HID   3584
#define NH    28
#define NKV   4
#define HD    128
#define SEQ   2048
#define DQ    (NH*HD)     // 3584
#define DKV   (NKV*HD)    // 512
#define GRP   128
#define NG    28          // k-groups of 128 (HID/128 == DQ/128)

// ---------------- device scratch ----------------
// INT8 transposed weights Wt[n][k] = (w - z), exact
__device__ int8_t g_WqT[(size_t)DQ * HID];
__device__ int8_t g_WkT[(size_t)DKV * HID];
__device__ int8_t g_WvT[(size_t)DKV * HID];
__device__ int8_t g_WoT[(size_t)HID * DQ];
// two-level int8 activations + per (row, group) scales
__device__ int8_t g_X8a[SEQ * HID], g_X8b[SEQ * HID];
__device__ float  g_sxx[SEQ * NG];
// fp32 projection outputs
__device__ float g_Q[SEQ * DQ];
__device__ float g_K[SEQ * DKV];
__device__ float g_V[SEQ * DKV];
// attention inputs, bf16 hi/lo
__device__ __nv_bfloat16 g_Qbh[SEQ * DQ],  g_Qbl[SEQ * DQ];
__device__ __nv_bfloat16 g_Kbh[SEQ * DKV], g_Kbl[SEQ * DKV];
__device__ __nv_bfloat16 g_Vth[(size_t)DKV * SEQ], g_Vtl[(size_t)DKV * SEQ];
// attention output fp32 + its int8 quantization
__device__ float  g_Ob[SEQ * DQ];
__device__ int8_t g_Ob8a[SEQ * DQ], g_Ob8b[SEQ * DQ];
__device__ float  g_sxo[SEQ * NG];

// ---------------- helpers ----------------
__device__ __forceinline__ unsigned sptr(const void* p) {
    return (unsigned)__cvta_generic_to_shared(p);
}

#define CP_ASYNC16(dst, src) \
    asm volatile("cp.async.cg.shared.global [%0], [%1], 16;\n" :: "r"(dst), "l"(src))
#define CP_COMMIT() asm volatile("cp.async.commit_group;\n")

#define MMA_BF16(C, Aa, Bb) \
    asm volatile("mma.sync.aligned.m16n8k16.row.col.f32.bf16.bf16.f32 " \
        "{%0,%1,%2,%3},{%4,%5,%6,%7},{%8,%9},{%0,%1,%2,%3};" \
        : "+f"(C[0]), "+f"(C[1]), "+f"(C[2]), "+f"(C[3]) \
        : "r"(Aa[0]), "r"(Aa[1]), "r"(Aa[2]), "r"(Aa[3]), "r"(Bb[0]), "r"(Bb[1]))

#define MMA_S8(C, Aa, Bb) \
    asm volatile("mma.sync.aligned.m16n8k32.row.col.s32.s8.s8.s32 " \
        "{%0,%1,%2,%3},{%4,%5,%6,%7},{%8,%9},{%0,%1,%2,%3};" \
        : "+r"(C[0]), "+r"(C[1]), "+r"(C[2]), "+r"(C[3]) \
        : "r"(Aa[0]), "r"(Aa[1]), "r"(Aa[2]), "r"(Aa[3]), "r"(Bb[0]), "r"(Bb[1]))

__device__ __forceinline__ void bsplit(float v, __nv_bfloat16& hi, __nv_bfloat16& lo) {
    hi = __float2bfloat16_rn(v);
    lo = __float2bfloat16_rn(v - __bfloat162float(hi));
}

__device__ __forceinline__ void packhl(float a, float b, unsigned& wh, unsigned& wl) {
    __nv_bfloat16 ha, la, hb, lb;
    bsplit(a, ha, la);
    bsplit(b, hb, lb);
    __nv_bfloat162 th; th.x = ha; th.y = hb;
    __nv_bfloat162 tl; tl.x = la; tl.y = lb;
    memcpy(&wh, &th, 4);
    memcpy(&wl, &tl, 4);
}

// ---------------- AWQ dequant -> transposed INT8 Wt[n][k] (exact) ----------------
__global__ void dequantTI8_kernel(const int* __restrict__ qw, const int* __restrict__ qz,
                                  int8_t* __restrict__ W, int din, int dout) {
    int idx = blockIdx.x * blockDim.x + threadIdx.x;
    int total = dout * (din >> 3);
    if (idx >= total) return;
    int n    = idx % dout;
    int kblk = idx / dout;
    int dout8 = dout >> 3;
    int pcol = n >> 3;
    int shift = (n & 7) * 4;
    int grp = (kblk * 8) >> 7;
    int z = (qz[(size_t)grp * dout8 + pcol] >> shift) & 0xF;
    int8_t hv[8];
#pragma unroll
    for (int j = 0; j < 8; j++) {
        int k = kblk * 8 + j;
        int w = (qw[(size_t)k * dout8 + pcol] >> shift) & 0xF;
        hv[j] = (int8_t)(w - z);
    }
    size_t off = (size_t)n * din + kblk * 8;
    *(uint2*)&W[off] = *(uint2*)hv;
}

// ---------------- two-level int8 quantization: one warp per 128-k group ----------------
__global__ void quantX_kernel(const float* __restrict__ in,
                              int8_t* __restrict__ qa, int8_t* __restrict__ qb,
                              float* __restrict__ sx, int total_groups) {
    int wgi  = (blockIdx.x * blockDim.x + threadIdx.x) >> 5;
    int lane = threadIdx.x & 31;
    if (wgi >= total_groups) return;
    int row = wgi / NG, grp = wgi - row * NG;
    size_t base = (size_t)row * (NG * 128) + grp * 128 + lane * 4;
    float4 v = *(const float4*)&in[base];
    float am = fmaxf(fmaxf(fabsf(v.x), fabsf(v.y)), fmaxf(fabsf(v.z), fabsf(v.w)));
#pragma unroll
    for (int o = 16; o; o >>= 1) am = fmaxf(am, __shfl_xor_sync(0xffffffffu, am, o));
    float s   = am * (1.0f / 127.0f);
    float inv = (am > 0.f) ? 127.0f / am : 0.f;
    float xs[4] = { v.x, v.y, v.z, v.w };
    unsigned wa = 0, wb = 0;
#pragma unroll
    for (int i = 0; i < 4; i++) {
        float xq = xs[i] * inv;
        int ai = __float2int_rn(xq);
        float r2 = xq - (float)ai;
        int bi = __float2int_rn(r2 * 252.0f);
        wa |= ((unsigned)ai & 0xFFu) << (8 * i);
        wb |= ((unsigned)bi & 0xFFu) << (8 * i);
    }
    ((unsigned*)qa)[base >> 2] = wa;
    ((unsigned*)qb)[base >> 2] = wb;
    if (lane == 0) sx[(size_t)row * NG + grp] = s;
}

// ---------------- INT8 group-scaled tensor-core GEMM ----------------
// C[M,N] = sum_g sx[row][g]*sc[g][n] * ((Aa + Ab/252)[M,Kg] @ W[N,Kg]^T) + bias
// 128x128x32 tile, 256 thr (8 warps 2x4), warp tile 64x32, imma m16n8k32.
#define I8STRW 12                 // smem row stride in words (48 B for 32 B data)
#define ITW (128*I8STRW)          // 1536 words per array per stage
#define ISTAGE (3*ITW)            // Aa|Ab|W  = 4608 words
#define IGEMM_SMEM (2*ISTAGE*4)   // 36864 B

#define IGEMM_BODY(NB, NN, HASB)                                                  \
    extern __shared__ unsigned smu[];                                             \
    int tid  = threadIdx.x;                                                       \
    int lane = tid & 31;                                                          \
    int wid  = tid >> 5;                                                          \
    int gid  = lane >> 2, tig = lane & 3;                                         \
    int warp_m = wid >> 2;                                                        \
    int warp_n = wid & 3;                                                         \
    int srow = tid >> 1;                                                          \
    int half = tid & 1;                                                           \
    size_t agoff = (size_t)(blockIdx.y * 128 + srow) * (NG*128) + half * 16;      \
    size_t bgoff = (size_t)((NB) * 128 + srow) * (NG*128) + half * 16;            \
    unsigned smbase = sptr(smu);                                                  \
    float acc[4][4][4];                                                           \
    int p1[4][4][4], p2[4][4][4];                                                 \
    _Pragma("unroll")                                                             \
    for (int mt = 0; mt < 4; mt++)                                                \
        _Pragma("unroll")                                                         \
        for (int nt = 0; nt < 4; nt++)                                            \
            _Pragma("unroll")                                                     \
            for (int i = 0; i < 4; i++) {                                         \
                acc[mt][nt][i] = 0.f; p1[mt][nt][i] = 0; p2[mt][nt][i] = 0;       \
            }                                                                     \
    const int NT = NG * 4;                                                        \
    IGISSUE(0, 0);                                                                \
    for (int kt = 0; kt < NT; kt++) {                                             \
        int cur = kt & 1;                                                         \
        if (kt + 1 < NT) {                                                        \
            IGISSUE(kt + 1, 1 - cur);                                             \
            asm volatile("cp.async.wait_group 1;\n");                             \
        } else {                                                                  \
            asm volatile("cp.async.wait_group 0;\n");                             \
        }                                                                         \
        __syncthreads();                                                          \
        const unsigned* SAa = smu + cur * ISTAGE;                                 \
        const unsigned* SAb = SAa + ITW;                                          \
        const unsigned* SW  = SAa + 2 * ITW;                                      \
        unsigned b[4][2];                                                         \
        _Pragma("unroll")                                                         \
        for (int nt = 0; nt < 4; nt++) {                                          \
            int nb2 = (warp_n * 32 + nt * 8 + gid) * I8STRW + tig;                \
            b[nt][0] = SW[nb2]; b[nt][1] = SW[nb2 + 4];                           \
        }                                                                         \
        _Pragma("unroll")                                                         \
        for (int mt = 0; mt < 4; mt++) {                                          \
            int ab = (warp_m * 64 + mt * 16 + gid) * I8STRW + tig;                \
            unsigned aa[4] = { SAa[ab], SAa[ab + 8*I8STRW], SAa[ab + 4], SAa[ab + 8*I8STRW + 4] }; \
            unsigned ar[4] = { SAb[ab], SAb[ab + 8*I8STRW], SAb[ab + 4], SAb[ab + 8*I8STRW + 4] }; \
            _Pragma("unroll")                                                     \
            for (int nt = 0; nt < 4; nt++) {                                      \
                MMA_S8(p1[mt][nt], aa, b[nt]);                                    \
                MMA_S8(p2[mt][nt], ar, b[nt]);                                    \
            }                                                                     \
        }                                                                         \
        __syncthreads();                                                          \
        if ((kt & 3) == 3) {                                                      \
            int g = kt >> 2;                                                      \
            float sx0[4], sx1[4];                                                 \
            _Pragma("unroll")                                                     \
            for (int mt = 0; mt < 4; mt++) {                                      \
                int row = blockIdx.y * 128 + warp_m * 64 + mt * 16 + gid;         \
                sx0[mt] = sxa[(size_t)row * NG + g];                              \
                sx1[mt] = sxa[(size_t)(row + 8) * NG + g];                        \
            }                                                                     \
            _Pragma("unroll")                                                     \
            for (int nt = 0; nt < 4; nt++) {                                      \
                int col = (NB) * 128 + warp_n * 32 + nt * 8 + tig * 2;            \
                float2 s2 = *(const float2*)&sc[(size_t)g * (NN) + col];          \
                _Pragma("unroll")                                                 \
                for (int mt = 0; mt < 4; mt++) {                                  \
                    const float I252 = 1.0f / 252.0f;                             \
                    float f0 = ((float)p1[mt][nt][0] + (float)p2[mt][nt][0] * I252) * sx0[mt]; \
                    float f1 = ((float)p1[mt][nt][1] + (float)p2[mt][nt][1] * I252) * sx0[mt]; \
                    float f2 = ((float)p1[mt][nt][2] + (float)p2[mt][nt][2] * I252) * sx1[mt]; \
                    float f3 = ((float)p1[mt][nt][3] + (float)p2[mt][nt][3] * I252) * sx1[mt]; \
                    acc[mt][nt][0] += f0 * s2.x;                                  \
                    acc[mt][nt][1] += f1 * s2.y;                                  \
                    acc[mt][nt][2] += f2 * s2.x;                                  \
                    acc[mt][nt][3] += f3 * s2.y;                                  \
                    p1[mt][nt][0] = 0; p1[mt][nt][1] = 0; p1[mt][nt][2] = 0; p1[mt][nt][3] = 0; \
                    p2[mt][nt][0] = 0; p2[mt][nt][1] = 0; p2[mt][nt][2] = 0; p2[mt][nt][3] = 0; \
                }                                                                 \
            }                                                                     \
        }                                                                         \
    }                                                                             \
    _Pragma("unroll")                                                             \
    for (int mt = 0; mt < 4; mt++) {                                              \
        int row = blockIdx.y * 128 + warp_m * 64 + mt * 16 + gid;                 \
        _Pragma("unroll")                                                         \
        for (int nt = 0; nt < 4; nt++) {                                          \
            int col = (NB) * 128 + warp_n * 32 + nt * 8 + tig * 2;                \
            float b0 = 0.f, b1 = 0.f;                                             \
            if (HASB) { b0 = bias[col]; b1 = bias[col + 1]; }                     \
            float2 v0 = { acc[mt][nt][0] + b0, acc[mt][nt][1] + b1 };             \
            float2 v1 = { acc[mt][nt][2] + b0, acc[mt][nt][3] + b1 };             \
            *(float2*)&C[(size_t)row * (NN) + col]       = v0;                    \
            *(float2*)&C[(size_t)(row + 8) * (NN) + col] = v1;                    \
        }                                                                         \
    }

#define IGISSUE(kt, stage) do {                                                   \
        unsigned d0 = smbase + ((stage) * ISTAGE + srow * I8STRW + half * 4) * 4; \
        const int8_t* pa = Aa8 + agoff + (size_t)(kt) * 32;                       \
        const int8_t* pr = Ab8 + agoff + (size_t)(kt) * 32;                       \
        const int8_t* pw = W8  + bgoff + (size_t)(kt) * 32;                       \
        CP_ASYNC16(d0,           pa);                                             \
        CP_ASYNC16(d0 + ITW*4,   pr);                                             \
        CP_ASYNC16(d0 + 2*ITW*4, pw);                                             \
        CP_COMMIT();                                                              \
    } while (0)

// fused Q/K/V projection
__global__ __launch_bounds__(256) void gemmsQKV(const int8_t* __restrict__ Aa8,
                                                const int8_t* __restrict__ Ab8,
                                                const float* __restrict__ sxa,
                                                const int8_t* __restrict__ W8Q,
                                                const int8_t* __restrict__ W8K,
                                                const int8_t* __restrict__ W8V,
                                                const float* __restrict__ scQ,
                                                const float* __restrict__ scK,
                                                const float* __restrict__ scV,
                                                const float* __restrict__ bQ,
                                                const float* __restrict__ bK,
                                                const float* __restrict__ bV,
                                                float* __restrict__ CQ,
                                                float* __restrict__ CK,
                                                float* __restrict__ CV) {
    int bx = blockIdx.x;
    const int8_t* W8;
    const float* sc;
    const float* bias;
    float* C;
    int N, nb;
    if (bx < 28)      { W8 = W8Q; sc = scQ; bias = bQ; C = CQ; N = DQ;  nb = bx; }
    else if (bx < 32) { W8 = W8K; sc = scK; bias = bK; C = CK; N = DKV; nb = bx - 28; }
    else              { W8 = W8V; sc = scV; bias = bV; C = CV; N = DKV; nb = bx - 32; }
    IGEMM_BODY(nb, N, true)
}

// O-projection (no bias)
__global__ __launch_bounds__(256) void gemmsO(const int8_t* __restrict__ Aa8,
                                              const int8_t* __restrict__ Ab8,
                                              const float* __restrict__ sxa,
                                              const int8_t* __restrict__ W8,
                                              const float* __restrict__ sc,
                                              const float* __restrict__ bias,
                                              float* __restrict__ C) {
    IGEMM_BODY((int)blockIdx.x, HID, false)
}
#undef IGISSUE

// ---------------- RoPE + bf16 hi/lo split of Q,K ----------------
__global__ void rope_split_kernel(const float* __restrict__ Q, const float* __restrict__ K,
                                  const int* __restrict__ pos,
                                  __nv_bfloat16* __restrict__ Qh, __nv_bfloat16* __restrict__ Ql,
                                  __nv_bfloat16* __restrict__ Kh, __nv_bfloat16* __restrict__ Kl) {
    int idx = blockIdx.x * blockDim.x + threadIdx.x;
    const int total = SEQ * (NH + NKV) * (HD / 2);
    if (idx >= total) return;
    int d = idx & 63;
    int h = (idx >> 6) & 31;
    int s = idx >> 11;
    float inv = expf((float)d * (-13.815510557964274f / 64.0f));
    float ang = (float)pos[s] * inv;
    float si, co;
    sincosf(ang, &si, &co);
    const float* p;
    __nv_bfloat16 *oh, *ol;
    size_t base;
    if (h < NH) {
        base = (size_t)s * DQ + h * HD;
        p = Q + base; oh = Qh; ol = Ql;
    } else {
        base = (size_t)s * DKV + (h - NH) * HD;
        p = K + base; oh = Kh; ol = Kl;
    }
    float x0 = p[d];
    float x1 = p[d + 64];
    float r0 = x0 * co - x1 * si;
    float r1 = x1 * co + x0 * si;
    __nv_bfloat16 h0, l0, h1, l1;
    bsplit(r0, h0, l0);
    bsplit(r1, h1, l1);
    oh[base + d]      = h0;  ol[base + d]      = l0;
    oh[base + d + 64] = h1;  ol[base + d + 64] = l1;
}

// ---------------- V: split + transpose -> Vt[dkv][seq] bf16 hi/lo ----------------
__global__ void vsplitT_kernel(const float* __restrict__ V,
                               __nv_bfloat16* __restrict__ Vth,
                               __nv_bfloat16* __restrict__ Vtl) {
    __shared__ float t[32][33];
    int d0 = blockIdx.x * 32;
    int s0 = blockIdx.y * 32;
    int tx = threadIdx.x, ty = threadIdx.y;
#pragma unroll
    for (int i = 0; i < 4; i++)
        t[ty + 8 * i][tx] = V[(size_t)(s0 + ty + 8 * i) * DKV + d0 + tx];
    __syncthreads();
#pragma unroll
    for (int i = 0; i < 4; i++) {
        float v = t[tx][ty + 8 * i];
        __nv_bfloat16 h, l;
        bsplit(v, h, l);
        size_t o = (size_t)(d0 + ty + 8 * i) * SEQ + s0 + tx;
        Vth[o] = h;
        Vtl[o] = l;
    }
}

// ---------------- FA2-style bf16x2 causal GQA attention (R12-proven) ----------------
#define QSTR2 68
#define KSTR2 68
#define VSTR2 36
#define O2QH 0
#define O2QL (O2QH + 128*QSTR2)
#define O2KH (O2QL + 128*QSTR2)
#define O2KL (O2KH + 2*64*KSTR2)
#define O2VH (O2KL + 2*64*KSTR2)
#define O2VL (O2VH + 2*128*VSTR2)
#define ATTN2_WORDS (O2VL + 2*128*VSTR2)
#define ATTN2_SMEM (ATTN2_WORDS * 4)       // 212992 B

__global__ __launch_bounds__(256) void attn_bf2(const __nv_bfloat16* __restrict__ Qh,
                                                const __nv_bfloat16* __restrict__ Ql,
                                                const __nv_bfloat16* __restrict__ Kh,
                                                const __nv_bfloat16* __restrict__ Kl,
                                                const __nv_bfloat16* __restrict__ Vth,
                                                const __nv_bfloat16* __restrict__ Vtl,
                                                float* __restrict__ Ob) {
    extern __shared__ unsigned smw[];
    int qb = (int)gridDim.x - 1 - (int)blockIdx.x;
    int h  = blockIdx.y;
    int hk = h / (NH / NKV);
    int tid  = threadIdx.x;
    int lane = tid & 31;
    int w    = tid >> 5;
    int gid  = lane >> 2, tig = lane & 3;
    unsigned smb = sptr(smw);

#pragma unroll
    for (int j = 0; j < 8; j++) {
        int c = tid + 256 * j;
        int r = c >> 4, wo = c & 15;
        size_t g = (size_t)(qb * 128 + r) * DQ + h * HD + wo * 8;
        unsigned ds = (unsigned)(r * QSTR2 + wo * 4) * 4;
        CP_ASYNC16(smb + O2QH * 4 + ds, Qh + g);
        CP_ASYNC16(smb + O2QL * 4 + ds, Ql + g);
    }
#define ISSUE_KV2(kb_, st_) do {                                                  \
        for (int j = 0; j < 4; j++) {                                             \
            int c = tid + 256 * j;                                                \
            int r = c >> 4, wo = c & 15;                                          \
            size_t g = (size_t)((kb_) * 64 + r) * DKV + hk * HD + wo * 8;         \
            unsigned ds = (unsigned)((st_) * 64 * KSTR2 + r * KSTR2 + wo * 4) * 4;\
            CP_ASYNC16(smb + O2KH * 4 + ds, Kh + g);                              \
            CP_ASYNC16(smb + O2KL * 4 + ds, Kl + g);                              \
        }                                                                         \
        for (int j = 0; j < 4; j++) {                                             \
            int c = tid + 256 * j;                                                \
            int r = c >> 3, wo = c & 7;                                           \
            size_t g = (size_t)(hk * HD + r) * SEQ + (kb_) * 64 + wo * 8;         \
            unsigned ds = (unsigned)((st_) * 128 * VSTR2 + r * VSTR2 + wo * 4) * 4;\
            CP_ASYNC16(smb + O2VH * 4 + ds, Vth + g);                             \
            CP_ASYNC16(smb + O2VL * 4 + ds, Vtl + g);                             \
        }                                                                         \
    } while (0)

    ISSUE_KV2(0, 0);
    CP_COMMIT();

    float oacc[16][4];
#pragma unroll
    for (int nt = 0; nt < 16; nt++)
#pragma unroll
        for (int i = 0; i < 4; i++) oacc[nt][i] = 0.f;

    float m0 = -1e30f, m1 = -1e30f, l0 = 0.f, l1 = 0.f;
    const float scale = 0.08838834764831845f;
    const unsigned* QHs = smw + O2QH;
    const unsigned* QLs = smw + O2QL;

    const int NKB = 2 * qb + 2;
    const int rg0 = qb * 128 + w * 16 + gid;
    const int rg1 = rg0 + 8;

    for (int kb = 0; kb < NKB; kb++) {
        int st = kb & 1;
        asm volatile("cp.async.wait_group 0;\n");
        __syncthreads();
        if (kb + 1 < NKB) {
            ISSUE_KV2(kb + 1, 1 - st);
            CP_COMMIT();
        }

        const unsigned* KHs = smw + O2KH + st * 64 * KSTR2;
        const unsigned* KLs = smw + O2KL + st * 64 * KSTR2;
        const unsigned* VHs = smw + O2VH + st * 128 * VSTR2;
        const unsigned* VLs = smw + O2VL + st * 128 * VSTR2;

        float sacc[8][4];
#pragma unroll
        for (int nt = 0; nt < 8; nt++)
#pragma unroll
            for (int i = 0; i < 4; i++) sacc[nt][i] = 0.f;

#pragma unroll
        for (int k16 = 0; k16 < 8; k16++) {
            int ab = (w * 16 + gid) * QSTR2 + 8 * k16 + tig;
            unsigned qa[4] = { QHs[ab], QHs[ab + 8 * QSTR2], QHs[ab + 4], QHs[ab + 8 * QSTR2 + 4] };
            unsigned ql[4] = { QLs[ab], QLs[ab + 8 * QSTR2], QLs[ab + 4], QLs[ab + 8 * QSTR2 + 4] };
#pragma unroll
            for (int nt = 0; nt < 8; nt++) {
                int nb2 = (nt * 8 + gid) * KSTR2 + 8 * k16 + tig;
                unsigned bh[2] = { KHs[nb2], KHs[nb2 + 4] };
                unsigned bl[2] = { KLs[nb2], KLs[nb2 + 4] };
                MMA_BF16(sacc[nt], qa, bh);
                MMA_BF16(sacc[nt], qa, bl);
                MMA_BF16(sacc[nt], ql, bh);
            }
        }

        bool diag = (kb >= 2 * qb);
        float mx0 = -1e30f, mx1 = -1e30f;
#pragma unroll
        for (int nt = 0; nt < 8; nt++) {
            float s0 = sacc[nt][0] * scale;
            float s1 = sacc[nt][1] * scale;
            float s2 = sacc[nt][2] * scale;
            float s3 = sacc[nt][3] * scale;
            if (diag) {
                int c0 = kb * 64 + nt * 8 + tig * 2;
                if (c0     > rg0) s0 = -1e30f;
                if (c0 + 1 > rg0) s1 = -1e30f;
                if (c0     > rg1) s2 = -1e30f;
                if (c0 + 1 > rg1) s3 = -1e30f;
            }
            sacc[nt][0] = s0; sacc[nt][1] = s1; sacc[nt][2] = s2; sacc[nt][3] = s3;
            mx0 = fmaxf(mx0, fmaxf(s0, s1));
            mx1 = fmaxf(mx1, fmaxf(s2, s3));
        }
        mx0 = fmaxf(mx0, __shfl_xor_sync(0xffffffffu, mx0, 1));
        mx0 = fmaxf(mx0, __shfl_xor_sync(0xffffffffu, mx0, 2));
        mx1 = fmaxf(mx1, __shfl_xor_sync(0xffffffffu, mx1, 1));
        mx1 = fmaxf(mx1, __shfl_xor_sync(0xffffffffu, mx1, 2));
        float mn0 = fmaxf(m0, mx0), mn1 = fmaxf(m1, mx1);
        float corr0 = __expf(m0 - mn0), corr1 = __expf(m1 - mn1);

        unsigned aPh[4][4], aPl[4][4];
        float la0 = 0.f, la1 = 0.f;
#pragma unroll
        for (int j = 0; j < 4; j++) {
#pragma unroll
            for (int half = 0; half < 2; half++) {
                int nt = 2 * j + half;
                float p0 = __expf(sacc[nt][0] - mn0);
                float p1 = __expf(sacc[nt][1] - mn0);
                float p2 = __expf(sacc[nt][2] - mn1);
                float p3 = __expf(sacc[nt][3] - mn1);
                la0 += p0 + p1;
                la1 += p2 + p3;
                packhl(p0, p1, aPh[j][2 * half],     aPl[j][2 * half]);
                packhl(p2, p3, aPh[j][2 * half + 1], aPl[j][2 * half + 1]);
            }
        }
        la0 += __shfl_xor_sync(0xffffffffu, la0, 1);
        la0 += __shfl_xor_sync(0xffffffffu, la0, 2);
        la1 += __shfl_xor_sync(0xffffffffu, la1, 1);
        la1 += __shfl_xor_sync(0xffffffffu, la1, 2);
        l0 = l0 * corr0 + la0;
        l1 = l1 * corr1 + la1;
        m0 = mn0; m1 = mn1;

#pragma unroll
        for (int nt = 0; nt < 16; nt++) {
            oacc[nt][0] *= corr0; oacc[nt][1] *= corr0;
            oacc[nt][2] *= corr1; oacc[nt][3] *= corr1;
        }

#pragma unroll
        for (int j = 0; j < 4; j++) {
#pragma unroll
            for (int nt = 0; nt < 16; nt++) {
                int vb = (nt * 8 + gid) * VSTR2 + 8 * j + tig;
                unsigned bh[2] = { VHs[vb], VHs[vb + 4] };
                unsigned bl[2] = { VLs[vb], VLs[vb + 4] };
                MMA_BF16(oacc[nt], aPh[j], bh);
                MMA_BF16(oacc[nt], aPh[j], bl);
                MMA_BF16(oacc[nt], aPl[j], bh);
            }
        }
    }
#undef ISSUE_KV2

    // finalize: write fp32 output (quantized by quantX afterwards)
    float inv0 = 1.0f / l0;
    float inv1 = 1.0f / l1;
    int gr = qb * 128 + w * 16 + gid;
#pragma unroll
    for (int nt = 0; nt < 16; nt++) {
        int c = h * HD + nt * 8 + tig * 2;
        float2 o0 = { oacc[nt][0] * inv0, oacc[nt][1] * inv0 };
        float2 o1 = { oacc[nt][2] * inv1, oacc[nt][3] * inv1 };
        *(float2*)&Ob[(size_t)gr * DQ + c]       = o0;
        *(float2*)&Ob[(size_t)(gr + 8) * DQ + c] = o1;
    }
}

// ---------------- launch ----------------
extern "C" void kernel_launch(void* const* d_in, const int* in_sizes, int n_in,
                              void* d_out, int out_size) {
    const float* x    = (const float*)d_in[0];
    const int*   pos  = (const int*)d_in[1];
    const int*   qw_q = (const int*)d_in[2];
    const int*   qz_q = (const int*)d_in[3];
    const float* sc_q = (const float*)d_in[4];
    const float* b_q  = (const float*)d_in[5];
    const int*   qw_k = (const int*)d_in[6];
    const int*   qz_k = (const int*)d_in[7];
    const float* sc_k = (const float*)d_in[8];
    const float* b_k  = (const float*)d_in[9];
    const int*   qw_v = (const int*)d_in[10];
    const int*   qz_v = (const int*)d_in[11];
    const float* sc_v = (const float*)d_in[12];
    const float* b_v  = (const float*)d_in[13];
    const int*   qw_o = (const int*)d_in[14];
    const int*   qz_o = (const int*)d_in[15];
    const float* sc_o = (const float*)d_in[16];
    float* out = (float*)d_out;

    int8_t *WqT,*WkT,*WvT,*WoT,*X8a,*X8b,*Ob8a,*Ob8b;
    __nv_bfloat16 *Qbh,*Qbl,*Kbh,*Kbl,*Vth,*Vtl;
    float *Qb,*Kb,*Vb,*Ob,*sxx,*sxo;
    cudaGetSymbolAddress((void**)&WqT, g_WqT);
    cudaGetSymbolAddress((void**)&WkT, g_WkT);
    cudaGetSymbolAddress((void**)&WvT, g_WvT);
    cudaGetSymbolAddress((void**)&WoT, g_WoT);
    cudaGetSymbolAddress((void**)&X8a, g_X8a);    cudaGetSymbolAddress((void**)&X8b, g_X8b);
    cudaGetSymbolAddress((void**)&Ob8a, g_Ob8a);  cudaGetSymbolAddress((void**)&Ob8b, g_Ob8b);
    cudaGetSymbolAddress((void**)&sxx, g_sxx);    cudaGetSymbolAddress((void**)&sxo, g_sxo);
    cudaGetSymbolAddress((void**)&Qbh, g_Qbh);    cudaGetSymbolAddress((void**)&Qbl, g_Qbl);
    cudaGetSymbolAddress((void**)&Kbh, g_Kbh);    cudaGetSymbolAddress((void**)&Kbl, g_Kbl);
    cudaGetSymbolAddress((void**)&Vth, g_Vth);    cudaGetSymbolAddress((void**)&Vtl, g_Vtl);
    cudaGetSymbolAddress((void**)&Qb, g_Q);
    cudaGetSymbolAddress((void**)&Kb, g_K);
    cudaGetSymbolAddress((void**)&Vb, g_V);
    cudaGetSymbolAddress((void**)&Ob, g_Ob);

    cudaFuncSetAttribute(gemmsQKV, cudaFuncAttributeMaxDynamicSharedMemorySize, IGEMM_SMEM);
    cudaFuncSetAttribute(gemmsO,   cudaFuncAttributeMaxDynamicSharedMemorySize, IGEMM_SMEM);
    cudaFuncSetAttribute(attn_bf2, cudaFuncAttributeMaxDynamicSharedMemorySize, ATTN2_SMEM);

    // dequant -> transposed INT8 weights (exact)
    {
        int t_q = DQ  * (HID / 8);
        int t_kv = DKV * (HID / 8);
        int t_o = HID * (DQ / 8);
        dequantTI8_kernel<<<(t_q  + 255) / 256, 256>>>(qw_q, qz_q, WqT, HID, DQ);
        dequantTI8_kernel<<<(t_kv + 255) / 256, 256>>>(qw_k, qz_k, WkT, HID, DKV);
        dequantTI8_kernel<<<(t_kv + 255) / 256, 256>>>(qw_v, qz_v, WvT, HID, DKV);
        dequantTI8_kernel<<<(t_o  + 255) / 256, 256>>>(qw_o, qz_o, WoT, DQ, HID);
    }

    // quantize activations (two-level int8, warp per 128-group)
    {
        int tg = SEQ * NG;                       // 57344 groups
        int thr = tg * 32;
        quantX_kernel<<<(thr + 255) / 256, 256>>>(x, X8a, X8b, sxx, tg);
    }

    // fused Q/K/V projections
    gemmsQKV<<<dim3(36, SEQ / 128), 256, IGEMM_SMEM>>>(
        X8a, X8b, sxx, WqT, WkT, WvT, sc_q, sc_k, sc_v, b_q, b_k, b_v, Qb, Kb, Vb);

    // RoPE + split
    {
        int total = SEQ * (NH + NKV) * (HD / 2);
        rope_split_kernel<<<(total + 255) / 256, 256>>>(Qb, Kb, pos, Qbh, Qbl, Kbh, Kbl);
    }
    vsplitT_kernel<<<dim3(DKV / 32, SEQ / 32), dim3(32, 8)>>>(Vb, Vth, Vtl);

    // attention -> fp32 Ob
    attn_bf2<<<dim3(SEQ / 128, NH), 256, ATTN2_SMEM>>>(Qbh, Qbl, Kbh, Kbl, Vth, Vtl, Ob);

    // quantize attention output, then O-projection
    {
        int tg = SEQ * NG;
        int thr = tg * 32;
        quantX_kernel<<<(thr + 255) / 256, 256>>>(Ob, Ob8a, Ob8b, sxo, tg);
    }
    gemmsO<<<dim3(HID / 128, SEQ / 128), 256, IGEMM_SMEM>>>(Ob8a, Ob8b, sxo, WoT, sc_o, nullptr, out);
}

// round 17
// speedup vs baseline: 1.6963x; 1.6963x over previous
#include <cuda_runtime.h>
#include <cuda_bf16.h>
#include <cstdint>
#include <cstddef>
#include <cstring>

// ---------------- problem constants ----------------
#define HID   3584
#define NH    28
#define NKV   4
#define HD    128
#define SEQ   2048
#define DQ    (NH*HD)     // 3584
#define DKV   (NKV*HD)    // 512
#define GRP   128

// ---------------- device scratch ----------------
__device__ __nv_bfloat16 g_WqT[(size_t)DQ * HID];
__device__ __nv_bfloat16 g_WkT[(size_t)DKV * HID];
__device__ __nv_bfloat16 g_WvT[(size_t)DKV * HID];
__device__ __nv_bfloat16 g_WoT[(size_t)HID * DQ];
__device__ __nv_bfloat16 g_Xh[SEQ * HID], g_Xl[SEQ * HID];
__device__ float g_Q[SEQ * DQ];
__device__ float g_K[SEQ * DKV];
__device__ float g_V[SEQ * DKV];
__device__ __nv_bfloat16 g_Qbh[SEQ * DQ],  g_Qbl[SEQ * DQ];
__device__ __nv_bfloat16 g_Kbh[SEQ * DKV], g_Kbl[SEQ * DKV];
__device__ __nv_bfloat16 g_Vth[(size_t)DKV * SEQ], g_Vtl[(size_t)DKV * SEQ];
__device__ __nv_bfloat16 g_Obh[SEQ * DQ], g_Obl[SEQ * DQ];

// ---------------- helpers ----------------
__device__ __forceinline__ unsigned sptr(const void* p) {
    return (unsigned)__cvta_generic_to_shared(p);
}

#define CP_ASYNC16(dst, src) \
    asm volatile("cp.async.cg.shared.global [%0], [%1], 16;\n" :: "r"(dst), "l"(src))
#define CP_COMMIT() asm volatile("cp.async.commit_group;\n")

#define MMA_BF16(C, Aa, Bb) \
    asm volatile("mma.sync.aligned.m16n8k16.row.col.f32.bf16.bf16.f32 " \
        "{%0,%1,%2,%3},{%4,%5,%6,%7},{%8,%9},{%0,%1,%2,%3};" \
        : "+f"(C[0]), "+f"(C[1]), "+f"(C[2]), "+f"(C[3]) \
        : "r"(Aa[0]), "r"(Aa[1]), "r"(Aa[2]), "r"(Aa[3]), "r"(Bb[0]), "r"(Bb[1]))

#define LDSM4(R0, R1, R2, R3, A) \
    asm volatile("ldmatrix.sync.aligned.m8n8.x4.shared.b16 {%0,%1,%2,%3}, [%4];" \
        : "=r"(R0), "=r"(R1), "=r"(R2), "=r"(R3) : "r"(A))

__device__ __forceinline__ void bsplit(float v, __nv_bfloat16& hi, __nv_bfloat16& lo) {
    hi = __float2bfloat16_rn(v);
    lo = __float2bfloat16_rn(v - __bfloat162float(hi));
}

__device__ __forceinline__ void packhl(float a, float b, unsigned& wh, unsigned& wl) {
    __nv_bfloat16 ha, la, hb, lb;
    bsplit(a, ha, la);
    bsplit(b, hb, lb);
    __nv_bfloat162 th; th.x = ha; th.y = hb;
    __nv_bfloat162 tl; tl.x = la; tl.y = lb;
    memcpy(&wh, &th, 4);
    memcpy(&wl, &tl, 4);
}

// ---------------- AWQ dequant -> transposed INT bf16 Wt[n][k] (exact) ----------------
__global__ void dequantTI_kernel(const int* __restrict__ qw, const int* __restrict__ qz,
                                 __nv_bfloat16* __restrict__ W,
                                 int din, int dout) {
    int idx = blockIdx.x * blockDim.x + threadIdx.x;
    int total = dout * (din >> 3);
    if (idx >= total) return;
    int n    = idx % dout;
    int kblk = idx / dout;
    int dout8 = dout >> 3;
    int pcol = n >> 3;
    int shift = (n & 7) * 4;
    int grp = (kblk * 8) >> 7;
    int z = (qz[(size_t)grp * dout8 + pcol] >> shift) & 0xF;
    __nv_bfloat16 hv[8];
#pragma unroll
    for (int j = 0; j < 8; j++) {
        int k = kblk * 8 + j;
        int w = (qw[(size_t)k * dout8 + pcol] >> shift) & 0xF;
        hv[j] = __float2bfloat16_rn((float)(w - z));
    }
    size_t off = (size_t)n * din + kblk * 8;
    *(float4*)&W[off] = *(float4*)hv;
}

// ---------------- split fp32 -> bf16 hi/lo ----------------
__global__ void splitb_kernel(const float* __restrict__ in,
                              __nv_bfloat16* __restrict__ hi,
                              __nv_bfloat16* __restrict__ lo, int n) {
    int i = blockIdx.x * blockDim.x + threadIdx.x;
    if (i < n) {
        __nv_bfloat16 h, l;
        bsplit(in[i], h, l);
        hi[i] = h;
        lo[i] = l;
    }
}

// ---------------- group-scaled bf16 GEMM core (R12 + ldmatrix) ----------------
#define BSTRW 20
#define TW (128*BSTRW)
#define SSTAGE (3*TW)
#define SGEMM_SMEM (2*SSTAGE*4)   // 61440 B

#define GEMM_BODY(NB, NN, KK, HASB)                                              \
    extern __shared__ unsigned smu[];                                            \
    int tid  = threadIdx.x;                                                      \
    int lane = tid & 31;                                                         \
    int wid  = tid >> 5;                                                         \
    int gid  = lane >> 2, tig = lane & 3;                                        \
    int warp_m = wid >> 2;                                                       \
    int warp_n = wid & 3;                                                        \
    int srow = tid >> 1;                                                         \
    int soff = (tid & 1) * 8;                                                    \
    size_t agoff = (size_t)(blockIdx.y * 128 + srow) * (KK) + (tid & 1) * 16;    \
    size_t bgoff = (size_t)((NB) * 128 + srow) * (KK) + (tid & 1) * 16;          \
    unsigned smbase = sptr(smu);                                                 \
    int l8 = lane & 7;                                                           \
    int tA = (lane >> 3) & 1, tB = (lane >> 4) & 1;                              \
    int arowoff = (warp_m * 64 + tA * 8 + l8) * BSTRW + tB * 4;                  \
    int browoff = (warp_n * 32 + tB * 8 + l8) * BSTRW + tA * 4;                  \
    float acc[4][4][4];                                                          \
    float part[4][4][4];                                                         \
    _Pragma("unroll")                                                            \
    for (int mt = 0; mt < 4; mt++)                                               \
        _Pragma("unroll")                                                        \
        for (int nt = 0; nt < 4; nt++)                                           \
            _Pragma("unroll")                                                    \
            for (int i = 0; i < 4; i++) { acc[mt][nt][i] = 0.f; part[mt][nt][i] = 0.f; } \
    const int NT = (KK) / 32;                                                    \
    GISSUE(0, 0);                                                                \
    for (int kt = 0; kt < NT; kt++) {                                            \
        int cur = kt & 1;                                                        \
        if (kt + 1 < NT) {                                                       \
            GISSUE(kt + 1, 1 - cur);                                             \
            asm volatile("cp.async.wait_group 1;\n");                            \
        } else {                                                                 \
            asm volatile("cp.async.wait_group 0;\n");                            \
        }                                                                        \
        __syncthreads();                                                         \
        unsigned ab_h = smbase + (unsigned)(cur * SSTAGE) * 4;                   \
        unsigned ab_l = ab_h + TW * 4;                                           \
        unsigned bb   = ab_h + 2 * TW * 4;                                       \
        _Pragma("unroll")                                                        \
        for (int ks = 0; ks < 2; ks++) {                                         \
            int ko = ks * 8;                                                     \
            unsigned b[4][2];                                                    \
            LDSM4(b[0][0], b[0][1], b[1][0], b[1][1],                            \
                  bb + (unsigned)(browoff + ko) * 4);                            \
            LDSM4(b[2][0], b[2][1], b[3][0], b[3][1],                            \
                  bb + (unsigned)(browoff + 16 * BSTRW + ko) * 4);               \
            _Pragma("unroll")                                                    \
            for (int mt = 0; mt < 4; mt++) {                                     \
                unsigned ah[4], al[4];                                           \
                unsigned ao = (unsigned)(arowoff + mt * 16 * BSTRW + ko) * 4;    \
                LDSM4(ah[0], ah[1], ah[2], ah[3], ab_h + ao);                    \
                LDSM4(al[0], al[1], al[2], al[3], ab_l + ao);                    \
                _Pragma("unroll")                                                \
                for (int nt = 0; nt < 4; nt++) {                                 \
                    MMA_BF16(part[mt][nt], ah, b[nt]);                           \
                    MMA_BF16(part[mt][nt], al, b[nt]);                           \
                }                                                                \
            }                                                                    \
        }                                                                        \
        __syncthreads();                                                         \
        if ((kt & 3) == 3) {                                                     \
            int g = kt >> 2;                                                     \
            _Pragma("unroll")                                                    \
            for (int nt = 0; nt < 4; nt++) {                                     \
                int col = (NB) * 128 + warp_n * 32 + nt * 8 + tig * 2;           \
                float2 s2 = *(const float2*)&sc[(size_t)g * (NN) + col];         \
                _Pragma("unroll")                                                \
                for (int mt = 0; mt < 4; mt++) {                                 \
                    acc[mt][nt][0] += part[mt][nt][0] * s2.x;                    \
                    acc[mt][nt][1] += part[mt][nt][1] * s2.y;                    \
                    acc[mt][nt][2] += part[mt][nt][2] * s2.x;                    \
                    acc[mt][nt][3] += part[mt][nt][3] * s2.y;                    \
                    part[mt][nt][0] = 0.f; part[mt][nt][1] = 0.f;                \
                    part[mt][nt][2] = 0.f; part[mt][nt][3] = 0.f;                \
                }                                                                \
            }                                                                    \
        }                                                                        \
    }                                                                            \
    _Pragma("unroll")                                                            \
    for (int mt = 0; mt < 4; mt++) {                                             \
        int row = blockIdx.y * 128 + warp_m * 64 + mt * 16 + gid;                \
        _Pragma("unroll")                                                        \
        for (int nt = 0; nt < 4; nt++) {                                         \
            int col = (NB) * 128 + warp_n * 32 + nt * 8 + tig * 2;               \
            float b0 = 0.f, b1 = 0.f;                                            \
            if (HASB) { b0 = bias[col]; b1 = bias[col + 1]; }                    \
            float2 v0 = { acc[mt][nt][0] + b0, acc[mt][nt][1] + b1 };            \
            float2 v1 = { acc[mt][nt][2] + b0, acc[mt][nt][3] + b1 };            \
            *(float2*)&C[(size_t)row * (NN) + col]       = v0;                   \
            *(float2*)&C[(size_t)(row + 8) * (NN) + col] = v1;                   \
        }                                                                        \
    }

#define GISSUE(kt, stage) do {                                               \
        unsigned d0 = smbase + ((stage) * SSTAGE + srow * BSTRW + soff) * 4; \
        const __nv_bfloat16* pah = Ah + agoff + (size_t)(kt) * 32;           \
        const __nv_bfloat16* pal = Al + agoff + (size_t)(kt) * 32;           \
        const __nv_bfloat16* pb  = Bt + bgoff + (size_t)(kt) * 32;           \
        CP_ASYNC16(d0,          pah); CP_ASYNC16(d0 + 16,          pah + 8); \
        CP_ASYNC16(d0 + TW*4,   pal); CP_ASYNC16(d0 + TW*4 + 16,   pal + 8); \
        CP_ASYNC16(d0 + 2*TW*4, pb);  CP_ASYNC16(d0 + 2*TW*4 + 16, pb + 8);  \
        CP_COMMIT();                                                         \
    } while (0)

// fused Q/K/V projection
__global__ __launch_bounds__(256) void gemmsQKV(const __nv_bfloat16* __restrict__ Ah,
                                                const __nv_bfloat16* __restrict__ Al,
                                                const __nv_bfloat16* __restrict__ BtQ,
                                                const __nv_bfloat16* __restrict__ BtK,
                                                const __nv_bfloat16* __restrict__ BtV,
                                                const float* __restrict__ scQ,
                                                const float* __restrict__ scK,
                                                const float* __restrict__ scV,
                                                const float* __restrict__ bQ,
                                                const float* __restrict__ bK,
                                                const float* __restrict__ bV,
                                                float* __restrict__ CQ,
                                                float* __restrict__ CK,
                                                float* __restrict__ CV) {
    int bx = blockIdx.x;
    const __nv_bfloat16* Bt;
    const float* sc;
    const float* bias;
    float* C;
    int N, nb;
    if (bx < 28)      { Bt = BtQ; sc = scQ; bias = bQ; C = CQ; N = DQ;  nb = bx; }
    else if (bx < 32) { Bt = BtK; sc = scK; bias = bK; C = CK; N = DKV; nb = bx - 28; }
    else              { Bt = BtV; sc = scV; bias = bV; C = CV; N = DKV; nb = bx - 32; }
    GEMM_BODY(nb, N, HID, true)
}

// O-projection (no bias)
__global__ __launch_bounds__(256) void gemmsO(const __nv_bfloat16* __restrict__ Ah,
                                              const __nv_bfloat16* __restrict__ Al,
                                              const __nv_bfloat16* __restrict__ Bt,
                                              const float* __restrict__ sc,
                                              const float* __restrict__ bias,
                                              float* __restrict__ C) {
    GEMM_BODY((int)blockIdx.x, HID, DQ, false)
}
#undef GISSUE

// ---------------- RoPE + bf16 hi/lo split of Q,K ----------------
__global__ void rope_split_kernel(const float* __restrict__ Q, const float* __restrict__ K,
                                  const int* __restrict__ pos,
                                  __nv_bfloat16* __restrict__ Qh, __nv_bfloat16* __restrict__ Ql,
                                  __nv_bfloat16* __restrict__ Kh, __nv_bfloat16* __restrict__ Kl) {
    int idx = blockIdx.x * blockDim.x + threadIdx.x;
    const int total = SEQ * (NH + NKV) * (HD / 2);
    if (idx >= total) return;
    int d = idx & 63;
    int h = (idx >> 6) & 31;
    int s = idx >> 11;
    float inv = expf((float)d * (-13.815510557964274f / 64.0f));
    float ang = (float)pos[s] * inv;
    float si, co;
    sincosf(ang, &si, &co);
    const float* p;
    __nv_bfloat16 *oh, *ol;
    size_t base;
    if (h < NH) {
        base = (size_t)s * DQ + h * HD;
        p = Q + base; oh = Qh; ol = Ql;
    } else {
        base = (size_t)s * DKV + (h - NH) * HD;
        p = K + base; oh = Kh; ol = Kl;
    }
    float x0 = p[d];
    float x1 = p[d + 64];
    float r0 = x0 * co - x1 * si;
    float r1 = x1 * co + x0 * si;
    __nv_bfloat16 h0, l0, h1, l1;
    bsplit(r0, h0, l0);
    bsplit(r1, h1, l1);
    oh[base + d]      = h0;  ol[base + d]      = l0;
    oh[base + d + 64] = h1;  ol[base + d + 64] = l1;
}

// ---------------- V: split + transpose -> Vt[dkv][seq] bf16 hi/lo ----------------
__global__ void vsplitT_kernel(const float* __restrict__ V,
                               __nv_bfloat16* __restrict__ Vth,
                               __nv_bfloat16* __restrict__ Vtl) {
    __shared__ float t[32][33];
    int d0 = blockIdx.x * 32;
    int s0 = blockIdx.y * 32;
    int tx = threadIdx.x, ty = threadIdx.y;
#pragma unroll
    for (int i = 0; i < 4; i++)
        t[ty + 8 * i][tx] = V[(size_t)(s0 + ty + 8 * i) * DKV + d0 + tx];
    __syncthreads();
#pragma unroll
    for (int i = 0; i < 4; i++) {
        float v = t[tx][ty + 8 * i];
        __nv_bfloat16 h, l;
        bsplit(v, h, l);
        size_t o = (size_t)(d0 + ty + 8 * i) * SEQ + s0 + tx;
        Vth[o] = h;
        Vtl[o] = l;
    }
}

// ---------------- FA2-style bf16x2 causal GQA attention (R12 + ldmatrix) ----------------
#define QSTR2 68
#define KSTR2 68
#define VSTR2 36
#define O2QH 0
#define O2QL (O2QH + 128*QSTR2)
#define O2KH (O2QL + 128*QSTR2)
#define O2KL (O2KH + 2*64*KSTR2)
#define O2VH (O2KL + 2*64*KSTR2)
#define O2VL (O2VH + 2*128*VSTR2)
#define ATTN2_WORDS (O2VL + 2*128*VSTR2)
#define ATTN2_SMEM (ATTN2_WORDS * 4)       // 212992 B

__global__ __launch_bounds__(256) void attn_bf2(const __nv_bfloat16* __restrict__ Qh,
                                                const __nv_bfloat16* __restrict__ Ql,
                                                const __nv_bfloat16* __restrict__ Kh,
                                                const __nv_bfloat16* __restrict__ Kl,
                                                const __nv_bfloat16* __restrict__ Vth,
                                                const __nv_bfloat16* __restrict__ Vtl,
                                                __nv_bfloat16* __restrict__ Oh,
                                                __nv_bfloat16* __restrict__ Ol) {
    extern __shared__ unsigned smw[];
    int qb = (int)gridDim.x - 1 - (int)blockIdx.x;
    int h  = blockIdx.y;
    int hk = h / (NH / NKV);
    int tid  = threadIdx.x;
    int lane = tid & 31;
    int w    = tid >> 5;
    int gid  = lane >> 2, tig = lane & 3;
    unsigned smb = sptr(smw);

    int l8 = lane & 7;
    int tA = (lane >> 3) & 1, tB = (lane >> 4) & 1;
    int qrowoff = (w * 16 + tA * 8 + l8) * QSTR2 + tB * 4;
    int krowoff = (tB * 8 + l8) * KSTR2 + tA * 4;
    int vrowoff = (tB * 8 + l8) * VSTR2 + tA * 4;

#pragma unroll
    for (int j = 0; j < 8; j++) {
        int c = tid + 256 * j;
        int r = c >> 4, wo = c & 15;
        size_t g = (size_t)(qb * 128 + r) * DQ + h * HD + wo * 8;
        unsigned ds = (unsigned)(r * QSTR2 + wo * 4) * 4;
        CP_ASYNC16(smb + O2QH * 4 + ds, Qh + g);
        CP_ASYNC16(smb + O2QL * 4 + ds, Ql + g);
    }
#define ISSUE_KV2(kb_, st_) do {                                                  \
        for (int j = 0; j < 4; j++) {                                             \
            int c = tid + 256 * j;                                                \
            int r = c >> 4, wo = c & 15;                                          \
            size_t g = (size_t)((kb_) * 64 + r) * DKV + hk * HD + wo * 8;         \
            unsigned ds = (unsigned)((st_) * 64 * KSTR2 + r * KSTR2 + wo * 4) * 4;\
            CP_ASYNC16(smb + O2KH * 4 + ds, Kh + g);                              \
            CP_ASYNC16(smb + O2KL * 4 + ds, Kl + g);                              \
        }                                                                         \
        for (int j = 0; j < 4; j++) {                                             \
            int c = tid + 256 * j;                                                \
            int r = c >> 3, wo = c & 7;                                           \
            size_t g = (size_t)(hk * HD + r) * SEQ + (kb_) * 64 + wo * 8;         \
            unsigned ds = (unsigned)((st_) * 128 * VSTR2 + r * VSTR2 + wo * 4) * 4;\
            CP_ASYNC16(smb + O2VH * 4 + ds, Vth + g);                             \
            CP_ASYNC16(smb + O2VL * 4 + ds, Vtl + g);                             \
        }                                                                         \
    } while (0)

    ISSUE_KV2(0, 0);
    CP_COMMIT();

    float oacc[16][4];
#pragma unroll
    for (int nt = 0; nt < 16; nt++)
#pragma unroll
        for (int i = 0; i < 4; i++) oacc[nt][i] = 0.f;

    float m0 = -1e30f, m1 = -1e30f, l0 = 0.f, l1 = 0.f;
    const float scale = 0.08838834764831845f;
    unsigned qb_h = smb + O2QH * 4;
    unsigned qb_l = smb + O2QL * 4;

    const int NKB = 2 * qb + 2;
    const int rg0 = qb * 128 + w * 16 + gid;
    const int rg1 = rg0 + 8;

    for (int kb = 0; kb < NKB; kb++) {
        int st = kb & 1;
        asm volatile("cp.async.wait_group 0;\n");
        __syncthreads();
        if (kb + 1 < NKB) {
            ISSUE_KV2(kb + 1, 1 - st);
            CP_COMMIT();
        }

        unsigned kb_h = smb + (O2KH + st * 64 * KSTR2) * 4;
        unsigned kb_l = smb + (O2KL + st * 64 * KSTR2) * 4;
        unsigned vb_h = smb + (O2VH + st * 128 * VSTR2) * 4;
        unsigned vb_l = smb + (O2VL + st * 128 * VSTR2) * 4;

        // ---- S = Q @ K^T : warp tile 16 rows x 64 cols (ldmatrix frags) ----
        float sacc[8][4];
#pragma unroll
        for (int nt = 0; nt < 8; nt++)
#pragma unroll
            for (int i = 0; i < 4; i++) sacc[nt][i] = 0.f;

#pragma unroll
        for (int k16 = 0; k16 < 8; k16++) {
            unsigned qa[4], qlr[4];
            unsigned qo = (unsigned)(qrowoff + 8 * k16) * 4;
            LDSM4(qa[0], qa[1], qa[2], qa[3], qb_h + qo);
            LDSM4(qlr[0], qlr[1], qlr[2], qlr[3], qb_l + qo);
#pragma unroll
            for (int ntp = 0; ntp < 4; ntp++) {
                unsigned kh4[4], kl4[4];
                unsigned ko = (unsigned)(krowoff + ntp * 16 * KSTR2 + 8 * k16) * 4;
                LDSM4(kh4[0], kh4[1], kh4[2], kh4[3], kb_h + ko);
                LDSM4(kl4[0], kl4[1], kl4[2], kl4[3], kb_l + ko);
#pragma unroll
                for (int h2 = 0; h2 < 2; h2++) {
                    int nt = 2 * ntp + h2;
                    unsigned bh[2] = { kh4[2 * h2], kh4[2 * h2 + 1] };
                    unsigned bl[2] = { kl4[2 * h2], kl4[2 * h2 + 1] };
                    MMA_BF16(sacc[nt], qa, bh);
                    MMA_BF16(sacc[nt], qa, bl);
                    MMA_BF16(sacc[nt], qlr, bh);
                }
            }
        }

        bool diag = (kb >= 2 * qb);
        float mx0 = -1e30f, mx1 = -1e30f;
#pragma unroll
        for (int nt = 0; nt < 8; nt++) {
            float s0 = sacc[nt][0] * scale;
            float s1 = sacc[nt][1] * scale;
            float s2 = sacc[nt][2] * scale;
            float s3 = sacc[nt][3] * scale;
            if (diag) {
                int c0 = kb * 64 + nt * 8 + tig * 2;
                if (c0     > rg0) s0 = -1e30f;
                if (c0 + 1 > rg0) s1 = -1e30f;
                if (c0     > rg1) s2 = -1e30f;
                if (c0 + 1 > rg1) s3 = -1e30f;
            }
            sacc[nt][0] = s0; sacc[nt][1] = s1; sacc[nt][2] = s2; sacc[nt][3] = s3;
            mx0 = fmaxf(mx0, fmaxf(s0, s1));
            mx1 = fmaxf(mx1, fmaxf(s2, s3));
        }
        mx0 = fmaxf(mx0, __shfl_xor_sync(0xffffffffu, mx0, 1));
        mx0 = fmaxf(mx0, __shfl_xor_sync(0xffffffffu, mx0, 2));
        mx1 = fmaxf(mx1, __shfl_xor_sync(0xffffffffu, mx1, 1));
        mx1 = fmaxf(mx1, __shfl_xor_sync(0xffffffffu, mx1, 2));
        float mn0 = fmaxf(m0, mx0), mn1 = fmaxf(m1, mx1);
        float corr0 = __expf(m0 - mn0), corr1 = __expf(m1 - mn1);

        unsigned aPh[4][4], aPl[4][4];
        float la0 = 0.f, la1 = 0.f;
#pragma unroll
        for (int j = 0; j < 4; j++) {
#pragma unroll
            for (int half = 0; half < 2; half++) {
                int nt = 2 * j + half;
                float p0 = __expf(sacc[nt][0] - mn0);
                float p1 = __expf(sacc[nt][1] - mn0);
                float p2 = __expf(sacc[nt][2] - mn1);
                float p3 = __expf(sacc[nt][3] - mn1);
                la0 += p0 + p1;
                la1 += p2 + p3;
                packhl(p0, p1, aPh[j][2 * half],     aPl[j][2 * half]);
                packhl(p2, p3, aPh[j][2 * half + 1], aPl[j][2 * half + 1]);
            }
        }
        la0 += __shfl_xor_sync(0xffffffffu, la0, 1);
        la0 += __shfl_xor_sync(0xffffffffu, la0, 2);
        la1 += __shfl_xor_sync(0xffffffffu, la1, 1);
        la1 += __shfl_xor_sync(0xffffffffu, la1, 2);
        l0 = l0 * corr0 + la0;
        l1 = l1 * corr1 + la1;
        m0 = mn0; m1 = mn1;

#pragma unroll
        for (int nt = 0; nt < 16; nt++) {
            oacc[nt][0] *= corr0; oacc[nt][1] *= corr0;
            oacc[nt][2] *= corr1; oacc[nt][3] *= corr1;
        }

        // ---- O += P @ V (P in registers, V frags via ldmatrix) ----
#pragma unroll
        for (int j = 0; j < 4; j++) {
#pragma unroll
            for (int ntp = 0; ntp < 8; ntp++) {
                unsigned vh4[4], vl4[4];
                unsigned vo = (unsigned)(vrowoff + ntp * 16 * VSTR2 + 8 * j) * 4;
                LDSM4(vh4[0], vh4[1], vh4[2], vh4[3], vb_h + vo);
                LDSM4(vl4[0], vl4[1], vl4[2], vl4[3], vb_l + vo);
#pragma unroll
                for (int h2 = 0; h2 < 2; h2++) {
                    int nt = 2 * ntp + h2;
                    unsigned bh[2] = { vh4[2 * h2], vh4[2 * h2 + 1] };
                    unsigned bl[2] = { vl4[2 * h2], vl4[2 * h2 + 1] };
                    MMA_BF16(oacc[nt], aPh[j], bh);
                    MMA_BF16(oacc[nt], aPh[j], bl);
                    MMA_BF16(oacc[nt], aPl[j], bh);
                }
            }
        }
    }
#undef ISSUE_KV2

    float inv0 = 1.0f / l0;
    float inv1 = 1.0f / l1;
    int gr = qb * 128 + w * 16 + gid;
#pragma unroll
    for (int nt = 0; nt < 16; nt++) {
        int c = h * HD + nt * 8 + tig * 2;
        unsigned wh0, wl0, wh1, wl1;
        packhl(oacc[nt][0] * inv0, oacc[nt][1] * inv0, wh0, wl0);
        packhl(oacc[nt][2] * inv1, oacc[nt][3] * inv1, wh1, wl1);
        *reinterpret_cast<unsigned*>(&Oh[(size_t)gr * DQ + c])       = wh0;
        *reinterpret_cast<unsigned*>(&Oh[(size_t)(gr + 8) * DQ + c]) = wh1;
        *reinterpret_cast<unsigned*>(&Ol[(size_t)gr * DQ + c])       = wl0;
        *reinterpret_cast<unsigned*>(&Ol[(size_t)(gr + 8) * DQ + c]) = wl1;
    }
}

// ---------------- launch ----------------
extern "C" void kernel_launch(void* const* d_in, const int* in_sizes, int n_in,
                              void* d_out, int out_size) {
    const float* x    = (const float*)d_in[0];
    const int*   pos  = (const int*)d_in[1];
    const int*   qw_q = (const int*)d_in[2];
    const int*   qz_q = (const int*)d_in[3];
    const float* sc_q = (const float*)d_in[4];
    const float* b_q  = (const float*)d_in[5];
    const int*   qw_k = (const int*)d_in[6];
    const int*   qz_k = (const int*)d_in[7];
    const float* sc_k = (const float*)d_in[8];
    const float* b_k  = (const float*)d_in[9];
    const int*   qw_v = (const int*)d_in[10];
    const int*   qz_v = (const int*)d_in[11];
    const float* sc_v = (const float*)d_in[12];
    const float* b_v  = (const float*)d_in[13];
    const int*   qw_o = (const int*)d_in[14];
    const int*   qz_o = (const int*)d_in[15];
    const float* sc_o = (const float*)d_in[16];
    float* out = (float*)d_out;

    __nv_bfloat16 *WqT,*WkT,*WvT,*WoT,*Xh,*Xl,*Obh,*Obl;
    __nv_bfloat16 *Qbh,*Qbl,*Kbh,*Kbl,*Vth,*Vtl;
    float *Qb,*Kb,*Vb;
    cudaGetSymbolAddress((void**)&WqT, g_WqT);
    cudaGetSymbolAddress((void**)&WkT, g_WkT);
    cudaGetSymbolAddress((void**)&WvT, g_WvT);
    cudaGetSymbolAddress((void**)&WoT, g_WoT);
    cudaGetSymbolAddress((void**)&Xh, g_Xh);      cudaGetSymbolAddress((void**)&Xl, g_Xl);
    cudaGetSymbolAddress((void**)&Obh, g_Obh);    cudaGetSymbolAddress((void**)&Obl, g_Obl);
    cudaGetSymbolAddress((void**)&Qbh, g_Qbh);    cudaGetSymbolAddress((void**)&Qbl, g_Qbl);
    cudaGetSymbolAddress((void**)&Kbh, g_Kbh);    cudaGetSymbolAddress((void**)&Kbl, g_Kbl);
    cudaGetSymbolAddress((void**)&Vth, g_Vth);    cudaGetSymbolAddress((void**)&Vtl, g_Vtl);
    cudaGetSymbolAddress((void**)&Qb, g_Q);
    cudaGetSymbolAddress((void**)&Kb, g_K);
    cudaGetSymbolAddress((void**)&Vb, g_V);

    cudaFuncSetAttribute(gemmsQKV, cudaFuncAttributeMaxDynamicSharedMemorySize, SGEMM_SMEM);
    cudaFuncSetAttribute(gemmsO,   cudaFuncAttributeMaxDynamicSharedMemorySize, SGEMM_SMEM);
    cudaFuncSetAttribute(attn_bf2, cudaFuncAttributeMaxDynamicSharedMemorySize, ATTN2_SMEM);

    // dequant -> transposed INT bf16 weights (exact)
    {
        int t_q = DQ  * (HID / 8);
        int t_kv = DKV * (HID / 8);
        int t_o = HID * (DQ / 8);
        dequantTI_kernel<<<(t_q  + 255) / 256, 256>>>(qw_q, qz_q, WqT, HID, DQ);
        dequantTI_kernel<<<(t_kv + 255) / 256, 256>>>(qw_k, qz_k, WkT, HID, DKV);
        dequantTI_kernel<<<(t_kv + 255) / 256, 256>>>(qw_v, qz_v, WvT, HID, DKV);
        dequantTI_kernel<<<(t_o  + 255) / 256, 256>>>(qw_o, qz_o, WoT, DQ, HID);
    }

    // split activations
    {
        int n = SEQ * HID;
        splitb_kernel<<<(n + 255) / 256, 256>>>(x, Xh, Xl, n);
    }

    // fused Q/K/V projections
    gemmsQKV<<<dim3(36, SEQ / 128), 256, SGEMM_SMEM>>>(
        Xh, Xl, WqT, WkT, WvT, sc_q, sc_k, sc_v, b_q, b_k, b_v, Qb, Kb, Vb);

    // RoPE + split
    {
        int total = SEQ * (NH + NKV) * (HD / 2);
        rope_split_kernel<<<(total + 255) / 256, 256>>>(Qb, Kb, pos, Qbh, Qbl, Kbh, Kbl);
    }
    vsplitT_kernel<<<dim3(DKV / 32, SEQ / 32), dim3(32, 8)>>>(Vb, Vth, Vtl);

    // attention (FA2 + ldmatrix)
    attn_bf2<<<dim3(SEQ / 128, NH), 256, ATTN2_SMEM>>>(Qbh, Qbl, Kbh, Kbl, Vth, Vtl, Obh, Obl);

    // output projection
    gemmsO<<<dim3(HID / 128, SEQ / 128), 256, SGEMM_SMEM>>>(Obh, Obl, WoT, sc_o, nullptr, out);
}